// round 6
// baseline (speedup 1.0000x reference)
#include <cuda_runtime.h>
#include <cooperative_groups.h>
#include <cstdint>
namespace cg = cooperative_groups;

// Problem constants
#define BATCH  8
#define NPTS   32768
#define NSAMP  8192
#define FEATC  256
#define TPB    512
#define NWARP  (TPB / 32)   // 16

// Sampled indices, produced by fps_kernel, consumed by gather_kernel.
__device__ int g_idx[BATCH * NSAMP];

// ---------------------------------------------------------------------------
// FPS kernel, templated on cluster size. One CSIZE-CTA cluster per batch.
// R4-proven skeleton: cluster.sync() for the cross-CTA exchange (R5 measured
// the mbarrier alternative SLOWER: 512 spinning try_waits lose to one HW
// cluster barrier). Per iteration:
//   compute + per-thread argmax (value + local j only; coords recovered
//   post-hoc on the winner lane)
//   -> warp argmax via REDUX (max of value bits, then min index among matches)
//   -> __syncthreads -> warp0 REDUX over the 16 warp winners
//   -> warp0 lanes 0..CSIZE-1 write the CTA candidate into rank r's
//      double-buffered DSMEM slot (parallel fan-out)
//   -> cluster.sync()
//   -> per-warp REDUX combine over the CSIZE slots -> global winner + coords.
//
// Tie-break everywhere: max value, then MIN global index (= jnp.argmax
// first-occurrence; indices globally unique so matches are one-hot). Value
// bits as u32 max is exact for nonnegative floats.
//
// Distance formula replicates XLA/NVPTX fp contraction exactly (bit-exact in
// R2/R4/R5):  d = fma(dz, dz, fma(dx, dx, dy*dy))
// ---------------------------------------------------------------------------
template <int CSIZE>
__global__ void __launch_bounds__(TPB, 1)
fps_kernel(const float* __restrict__ xyz)
{
    constexpr int PPC = NPTS / CSIZE;   // points per CTA
    constexpr int PPT = PPC / TPB;      // points per thread (4 or 8)

    cg::cluster_group cluster = cg::this_cluster();
    const int rank  = cluster.block_rank();
    const int batch = blockIdx.x / CSIZE;
    const int tid   = threadIdx.x;
    const int lane  = tid & 31;
    const int wid   = tid >> 5;

    const float* __restrict__ xb = xyz + (size_t)batch * NPTS * 3;

    __shared__ alignas(16) float s_warp[NWARP][8];      // per-warp winners
    __shared__ alignas(16) float s_slot[2][CSIZE][8];   // cluster candidates

    const int base = rank * PPC + tid;

    // Register-resident point coords and running min distances.
    float px[PPT], py[PPT], pz[PPT], md[PPT];
#pragma unroll
    for (int j = 0; j < PPT; j++) {
        const int p = base + j * TPB;
        px[j] = xb[3 * p + 0];
        py[j] = xb[3 * p + 1];
        pz[j] = xb[3 * p + 2];
        md[j] = 1e10f;            // BIG from the reference
    }

    // First sampled point is index 0 (deterministic variant).
    float cx = xb[0], cy = xb[1], cz = xb[2];
    if (rank == 0 && tid == 0) g_idx[batch * NSAMP] = 0;

    for (int k = 1; k < NSAMP; k++) {
        // --- per-thread: update min_dist, local argmax (value + local j) ---
        float bv;
        int   bj;
#pragma unroll
        for (int j = 0; j < PPT; j++) {
            const float dx = __fsub_rn(px[j], cx);
            const float dy = __fsub_rn(py[j], cy);
            const float dz = __fsub_rn(pz[j], cz);
            const float d  = __fmaf_rn(dz, dz,
                              __fmaf_rn(dx, dx, __fmul_rn(dy, dy)));
            const float m  = fminf(md[j], d);
            md[j] = m;
            if (j == 0) {
                bv = m; bj = 0;
            } else if (m > bv) {   // strict >: earlier (lower) index wins ties
                bv = m; bj = j;
            }
        }
        const uint32_t bi = (uint32_t)(base + bj * TPB);

        // --- warp argmax via REDUX ---
        const uint32_t uv = __float_as_uint(bv);            // bv >= 0
        const uint32_t kv = __reduce_max_sync(0xffffffffu, uv);
        const uint32_t cand = (uv == kv) ? bi : 0xffffffffu;
        const uint32_t ki = __reduce_min_sync(0xffffffffu, cand);
        if (bi == ki) {            // unique winner lane: recover coords here
            float bx = px[0], by = py[0], bz = pz[0];
#pragma unroll
            for (int j = 1; j < PPT; j++) {
                if (bj == j) { bx = px[j]; by = py[j]; bz = pz[j]; }
            }
            *(float4*)&s_warp[wid][0] =
                make_float4(__uint_as_float(kv), __uint_as_float(ki), bx, by);
            s_warp[wid][4] = bz;
        }
        __syncthreads();

        const int b = k & 1;

        // --- warp0: block argmax over 16 warp winners, fan out to all ranks ---
        if (wid == 0) {
            float sv = 0.f, sx = 0.f, sy = 0.f, sz = 0.f;
            uint32_t si = 0xffffffffu;
            if (lane < NWARP) {
                const float4 t = *(const float4*)&s_warp[lane][0];
                sv = t.x; si = __float_as_uint(t.y); sx = t.z; sy = t.w;
                sz = s_warp[lane][4];
            }
            const uint32_t uv2 = __float_as_uint(sv);
            const uint32_t kv2 = __reduce_max_sync(0xffffffffu, uv2);
            const uint32_t c2  = (uv2 == kv2) ? si : 0xffffffffu;
            const uint32_t ki2 = __reduce_min_sync(0xffffffffu, c2);
            const uint32_t m2  = __ballot_sync(0xffffffffu, c2 == ki2); // one-hot
            const int src = __ffs(m2) - 1;
            const float wx = __shfl_sync(0xffffffffu, sx, src);
            const float wy = __shfl_sync(0xffffffffu, sy, src);
            const float wz = __shfl_sync(0xffffffffu, sz, src);
            if (lane < CSIZE) {
                // lane r writes this CTA's candidate into rank r's slot row.
                // Ordering/visibility provided by cluster.sync() below.
                float* dst = (float*)cluster.map_shared_rank(
                    (void*)&s_slot[b][rank][0], lane);
                *(float4*)dst =
                    make_float4(__uint_as_float(kv2), __uint_as_float(ki2), wx, wy);
                dst[4] = wz;
            }
        }

        // release DSMEM stores + cluster barrier + acquire remote stores
        cluster.sync();

        // --- per-warp REDUX combine over the CSIZE slots ---
        float sv = 0.f, sx = 0.f, sy = 0.f, sz = 0.f;
        uint32_t si = 0xffffffffu;
        if (lane < CSIZE) {
            const float4 t = *(const float4*)&s_slot[b][lane][0];
            sv = t.x; si = __float_as_uint(t.y); sx = t.z; sy = t.w;
            sz = s_slot[b][lane][4];
        }
        const uint32_t uv3 = __float_as_uint(sv);
        const uint32_t kv3 = __reduce_max_sync(0xffffffffu, uv3);
        const uint32_t c3  = (uv3 == kv3) ? si : 0xffffffffu;
        const uint32_t ki3 = __reduce_min_sync(0xffffffffu, c3);
        const uint32_t m3  = __ballot_sync(0xffffffffu, c3 == ki3);    // one-hot
        const int src3 = __ffs(m3) - 1;
        cx = __shfl_sync(0xffffffffu, sx, src3);
        cy = __shfl_sync(0xffffffffu, sy, src3);
        cz = __shfl_sync(0xffffffffu, sz, src3);

        if (rank == 0 && tid == 0) g_idx[batch * NSAMP + k] = (int)ki3;
    }
}

// ---------------------------------------------------------------------------
// Gather kernel: one block per sampled row. 256 feature floats (64 x float4)
// plus the 3 xyz floats. Output: [xyz (B,S,3)] then [feature (B,S,256)].
// ---------------------------------------------------------------------------
__global__ void __launch_bounds__(64)
gather_kernel(const float* __restrict__ xyz, const float* __restrict__ feat,
              float* __restrict__ out)
{
    const int row = blockIdx.x;          // 0 .. BATCH*NSAMP-1
    const int b = row / NSAMP;
    const int p = g_idx[row];

    float* out_xyz  = out;
    float* out_feat = out + (size_t)BATCH * NSAMP * 3;

    const float4* src = (const float4*)(feat + ((size_t)b * NPTS + p) * FEATC);
    float4*       dst = (float4*)(out_feat + (size_t)row * FEATC);
    dst[threadIdx.x] = src[threadIdx.x];

    if (threadIdx.x < 3) {
        out_xyz[(size_t)row * 3 + threadIdx.x] =
            xyz[((size_t)b * NPTS + p) * 3 + threadIdx.x];
    }
}

static void launch_cluster(const void* fn, int csize, const float* xyz)
{
    cudaLaunchConfig_t cfg = {};
    cfg.gridDim  = dim3(BATCH * csize);
    cfg.blockDim = dim3(TPB);
    cfg.dynamicSmemBytes = 0;
    cfg.stream = 0;
    cudaLaunchAttribute a[1];
    a[0].id = cudaLaunchAttributeClusterDimension;
    a[0].val.clusterDim.x = csize;
    a[0].val.clusterDim.y = 1;
    a[0].val.clusterDim.z = 1;
    cfg.attrs = a;
    cfg.numAttrs = 1;
    cudaLaunchKernelEx(&cfg, (void (*)(const float*))fn, xyz);
}

extern "C" void kernel_launch(void* const* d_in, const int* in_sizes, int n_in,
                              void* d_out, int out_size)
{
    const float* xyz  = (const float*)d_in[0];
    const float* feat = (const float*)d_in[1];
    float*       out  = (float*)d_out;

    // Prefer a 16-CTA cluster (non-portable size); deterministic fallback to
    // the R4-proven 8-CTA configuration. Query-only host calls (capture-safe).
    cudaFuncSetAttribute(fps_kernel<16>,
                         cudaFuncAttributeNonPortableClusterSizeAllowed, 1);
    int maxc = 0;
    {
        cudaLaunchConfig_t q = {};
        q.gridDim  = dim3(BATCH * 16);
        q.blockDim = dim3(TPB);
        q.dynamicSmemBytes = 0;
        q.stream = 0;
        q.attrs = nullptr;
        q.numAttrs = 0;
        cudaOccupancyMaxPotentialClusterSize(&maxc, fps_kernel<16>, &q);
    }

    if (maxc >= 16) launch_cluster((const void*)fps_kernel<16>, 16, xyz);
    else            launch_cluster((const void*)fps_kernel<8>,   8, xyz);

    gather_kernel<<<BATCH * NSAMP, 64>>>(xyz, feat, out);
}

// round 7
// speedup vs baseline: 1.1431x; 1.1431x over previous
#include <cuda_runtime.h>
#include <cooperative_groups.h>
#include <cstdint>
namespace cg = cooperative_groups;

// Problem constants
#define BATCH  8
#define NPTS   32768
#define NSAMP  8192
#define FEATC  256
#define CSIZE  8                 // cluster size; 8 is the measured optimum
#define TPB    512
#define PPC    (NPTS / CSIZE)    // 4096 points per CTA
#define PPT    (PPC / TPB)       // 8 points per thread
#define NWARP  (TPB / 32)        // 16

// Sampled indices, produced by fps_kernel, consumed by gather_kernel.
__device__ int g_idx[BATCH * NSAMP];

// ---------------------------------------------------------------------------
// mbarrier helpers (scoping proven correct in R5: .release.cluster on remote
// arrive orders the producer's DSMEM stores; .acquire.cluster on the wait
// makes them visible to the consumer).
// ---------------------------------------------------------------------------
__device__ __forceinline__ uint32_t smem_u32(const void* p) {
    return (uint32_t)__cvta_generic_to_shared(p);
}
__device__ __forceinline__ void mbar_init(uint32_t a, uint32_t cnt) {
    asm volatile("mbarrier.init.shared.b64 [%0], %1;" :: "r"(a), "r"(cnt) : "memory");
}
__device__ __forceinline__ void mbar_arrive_remote(uint32_t local_a, uint32_t rank) {
    asm volatile(
        "{\n\t.reg .b32 ra;\n\t"
        "mapa.shared::cluster.u32 ra, %0, %1;\n\t"
        "mbarrier.arrive.release.cluster.shared::cluster.b64 _, [ra];\n\t}"
        :: "r"(local_a), "r"(rank) : "memory");
}
__device__ __forceinline__ void mbar_wait_cluster(uint32_t a, uint32_t parity) {
    asm volatile(
        "{\n\t.reg .pred P;\n\t"
        "W%=:\n\t"
        "mbarrier.try_wait.parity.acquire.cluster.shared::cta.b64 P, [%0], %1, 0x989680;\n\t"
        "@!P bra W%=;\n\t}"
        :: "r"(a), "r"(parity) : "memory");
}

// ---------------------------------------------------------------------------
// FPS kernel: one 8-CTA cluster per batch. R5 lesson: mbarrier exchange with
// ALL 512 threads polling loses to cluster.sync. R7 design: ONLY WARP 0 waits
// the mbarrier (TMA-consumer pattern); the other 15 warps park at
// __syncthreads and receive the winner via a 4-float smem broadcast.
//
// Per iteration:
//   all warps: compute + per-thread argmax -> warp REDUX -> winner lane
//     writes s_warp[wid] -> __syncthreads (A)
//   warp0 only: block REDUX over 16 warp winners; lanes 0..7 store the CTA
//     candidate into rank r's double-buffered DSMEM slot + remote arrive
//     (release.cluster, count=8); wait local mbar[b] (acquire.cluster);
//     REDUX-combine the 8 slots; lane0 writes {cx,cy,cz} to s_bcast;
//     rank0/lane0 writes g_idx.
//   __syncthreads (B); all warps read s_bcast.
//
// Protocol safety: an arrival on rank r's mbar[b] at iter k+2 is ordered
// after the producer passed its wait at k+1, which required rank r's arrival
// at k+1, which is after rank r's syncB(k) -- i.e. after rank r finished its
// wait+combine on buffer b at iter k. No phase overlap, no overwrite hazard.
// s_bcast single buffer: the k+1 write happens after syncA(k+1); every
// reader passed syncA(k+1) only after consuming the k value.
//
// Tie-break everywhere: max value, then MIN global index (= jnp.argmax
// first-occurrence; indices unique so matches are one-hot). Value bits as
// u32 max is exact for nonnegative floats.
// Distance formula replicates XLA/NVPTX fp contraction exactly (bit-exact
// R2/R4/R5/R6):  d = fma(dz, dz, fma(dx, dx, dy*dy))
// ---------------------------------------------------------------------------
__global__ void __cluster_dims__(CSIZE, 1, 1) __launch_bounds__(TPB, 1)
fps_kernel(const float* __restrict__ xyz)
{
    cg::cluster_group cluster = cg::this_cluster();
    const int rank  = cluster.block_rank();
    const int batch = blockIdx.x / CSIZE;
    const int tid   = threadIdx.x;
    const int lane  = tid & 31;
    const int wid   = tid >> 5;

    const float* __restrict__ xb = xyz + (size_t)batch * NPTS * 3;

    __shared__ alignas(16) float    s_warp[NWARP][8];      // per-warp winners
    __shared__ alignas(16) float    s_slot[2][CSIZE][8];   // cluster candidates
    __shared__ alignas(16) float    s_bcast[4];            // winner coords
    __shared__ alignas(8)  uint64_t s_mbar[2];

    if (tid == 0) {
        mbar_init(smem_u32(&s_mbar[0]), CSIZE);
        mbar_init(smem_u32(&s_mbar[1]), CSIZE);
    }
    cluster.sync();   // mbarrier init visible cluster-wide before any arrive

    const uint32_t mbar0 = smem_u32(&s_mbar[0]);
    const int base = rank * PPC + tid;

    // Register-resident point coords and running min distances.
    float px[PPT], py[PPT], pz[PPT], md[PPT];
#pragma unroll
    for (int j = 0; j < PPT; j++) {
        const int p = base + j * TPB;
        px[j] = xb[3 * p + 0];
        py[j] = xb[3 * p + 1];
        pz[j] = xb[3 * p + 2];
        md[j] = 1e10f;            // BIG from the reference
    }

    // First sampled point is index 0 (deterministic variant).
    float cx = xb[0], cy = xb[1], cz = xb[2];
    if (rank == 0 && tid == 0) g_idx[batch * NSAMP] = 0;

    uint32_t ph0 = 0, ph1 = 0;    // per-buffer wait parities (used by warp0)

    for (int k = 1; k < NSAMP; k++) {
        // --- per-thread: update min_dist, local argmax (value + local j) ---
        float bv;
        int   bj;
#pragma unroll
        for (int j = 0; j < PPT; j++) {
            const float dx = __fsub_rn(px[j], cx);
            const float dy = __fsub_rn(py[j], cy);
            const float dz = __fsub_rn(pz[j], cz);
            const float d  = __fmaf_rn(dz, dz,
                              __fmaf_rn(dx, dx, __fmul_rn(dy, dy)));
            const float m  = fminf(md[j], d);
            md[j] = m;
            if (j == 0) {
                bv = m; bj = 0;
            } else if (m > bv) {   // strict >: earlier (lower) index wins ties
                bv = m; bj = j;
            }
        }
        const uint32_t bi = (uint32_t)(base + bj * TPB);

        // --- warp argmax via REDUX ---
        const uint32_t uv = __float_as_uint(bv);            // bv >= 0
        const uint32_t kv = __reduce_max_sync(0xffffffffu, uv);
        const uint32_t cand = (uv == kv) ? bi : 0xffffffffu;
        const uint32_t ki = __reduce_min_sync(0xffffffffu, cand);
        if (bi == ki) {            // unique winner lane: recover coords here
            float bx = px[0], by = py[0], bz = pz[0];
#pragma unroll
            for (int j = 1; j < PPT; j++) {
                if (bj == j) { bx = px[j]; by = py[j]; bz = pz[j]; }
            }
            *(float4*)&s_warp[wid][0] =
                make_float4(__uint_as_float(kv), __uint_as_float(ki), bx, by);
            s_warp[wid][4] = bz;
        }
        __syncthreads();                                    // (A)

        const int b = k & 1;

        if (wid == 0) {
            // --- block argmax over 16 warp winners ---
            float sv = 0.f, sx = 0.f, sy = 0.f, sz = 0.f;
            uint32_t si = 0xffffffffu;
            if (lane < NWARP) {
                const float4 t = *(const float4*)&s_warp[lane][0];
                sv = t.x; si = __float_as_uint(t.y); sx = t.z; sy = t.w;
                sz = s_warp[lane][4];
            }
            const uint32_t uv2 = __float_as_uint(sv);
            const uint32_t kv2 = __reduce_max_sync(0xffffffffu, uv2);
            const uint32_t c2  = (uv2 == kv2) ? si : 0xffffffffu;
            const uint32_t ki2 = __reduce_min_sync(0xffffffffu, c2);
            const uint32_t m2  = __ballot_sync(0xffffffffu, c2 == ki2); // one-hot
            const int src = __ffs(m2) - 1;
            const float wx = __shfl_sync(0xffffffffu, sx, src);
            const float wy = __shfl_sync(0xffffffffu, sy, src);
            const float wz = __shfl_sync(0xffffffffu, sz, src);

            // --- publish: lane r -> rank r's slot + release-arrive ---
            if (lane < CSIZE) {
                float* dst = (float*)cluster.map_shared_rank(
                    (void*)&s_slot[b][rank][0], lane);
                *(float4*)dst =
                    make_float4(__uint_as_float(kv2), __uint_as_float(ki2), wx, wy);
                dst[4] = wz;
                mbar_arrive_remote(mbar0 + b * 8, lane);
            }

            // --- warp0 alone waits for all 8 candidates ---
            mbar_wait_cluster(mbar0 + b * 8, b ? ph1 : ph0);
            if (b) ph1 ^= 1; else ph0 ^= 1;

            // --- combine the 8 slots ---
            float qv = 0.f, qx = 0.f, qy = 0.f, qz = 0.f;
            uint32_t qi = 0xffffffffu;
            if (lane < CSIZE) {
                const float4 t = *(const float4*)&s_slot[b][lane][0];
                qv = t.x; qi = __float_as_uint(t.y); qx = t.z; qy = t.w;
                qz = s_slot[b][lane][4];
            }
            const uint32_t uv3 = __float_as_uint(qv);
            const uint32_t kv3 = __reduce_max_sync(0xffffffffu, uv3);
            const uint32_t c3  = (uv3 == kv3) ? qi : 0xffffffffu;
            const uint32_t ki3 = __reduce_min_sync(0xffffffffu, c3);
            const uint32_t m3  = __ballot_sync(0xffffffffu, c3 == ki3);
            const int src3 = __ffs(m3) - 1;
            const float nx = __shfl_sync(0xffffffffu, qx, src3);
            const float ny = __shfl_sync(0xffffffffu, qy, src3);
            const float nz = __shfl_sync(0xffffffffu, qz, src3);
            if (lane == 0) {
                *(float4*)&s_bcast[0] = make_float4(nx, ny, nz, 0.f);
                if (rank == 0) g_idx[batch * NSAMP + k] = (int)ki3;
            }
        }
        __syncthreads();                                    // (B)

        const float4 w = *(const float4*)&s_bcast[0];
        cx = w.x; cy = w.y; cz = w.z;
    }
}

// ---------------------------------------------------------------------------
// Gather kernel: one block per sampled row. 256 feature floats (64 x float4)
// plus the 3 xyz floats. Output: [xyz (B,S,3)] then [feature (B,S,256)].
// ---------------------------------------------------------------------------
__global__ void __launch_bounds__(64)
gather_kernel(const float* __restrict__ xyz, const float* __restrict__ feat,
              float* __restrict__ out)
{
    const int row = blockIdx.x;          // 0 .. BATCH*NSAMP-1
    const int b = row / NSAMP;
    const int p = g_idx[row];

    float* out_xyz  = out;
    float* out_feat = out + (size_t)BATCH * NSAMP * 3;

    const float4* src = (const float4*)(feat + ((size_t)b * NPTS + p) * FEATC);
    float4*       dst = (float4*)(out_feat + (size_t)row * FEATC);
    dst[threadIdx.x] = src[threadIdx.x];

    if (threadIdx.x < 3) {
        out_xyz[(size_t)row * 3 + threadIdx.x] =
            xyz[((size_t)b * NPTS + p) * 3 + threadIdx.x];
    }
}

extern "C" void kernel_launch(void* const* d_in, const int* in_sizes, int n_in,
                              void* d_out, int out_size)
{
    const float* xyz  = (const float*)d_in[0];
    const float* feat = (const float*)d_in[1];
    float*       out  = (float*)d_out;

    fps_kernel<<<BATCH * CSIZE, TPB>>>(xyz);
    gather_kernel<<<BATCH * NSAMP, 64>>>(xyz, feat, out);
}

// round 8
// speedup vs baseline: 1.3146x; 1.1501x over previous
#include <cuda_runtime.h>
#include <cooperative_groups.h>
#include <cstdint>
namespace cg = cooperative_groups;

// Problem constants
#define BATCH  8
#define NPTS   32768
#define NSAMP  8192
#define FEATC  256
#define CSIZE  8                 // cluster size; 8 measured optimal (R6: 16 worse)
#define TPB    512
#define PPC    (NPTS / CSIZE)    // 4096 points per CTA
#define PPT    (PPC / TPB)       // 8 points per thread
#define NPAIR  (PPT / 2)         // 4 packed pairs per thread
#define NWARP  (TPB / 32)        // 16

// Sampled indices, produced by fps_kernel, consumed by gather_kernel.
__device__ int g_idx[BATCH * NSAMP];

// ---------------------------------------------------------------------------
// Packed f32x2 helpers (sm_103a). Each packed op = two independent IEEE .rn
// f32 lane ops, so results are bit-identical to the scalar forms. mov.b64
// pack/unpack is register-pair renaming (free or 1 MOV).
// ---------------------------------------------------------------------------
__device__ __forceinline__ uint64_t pk2(float lo, float hi) {
    uint64_t r; asm("mov.b64 %0, {%1, %2};" : "=l"(r) : "f"(lo), "f"(hi)); return r;
}
__device__ __forceinline__ void upk2(float& lo, float& hi, uint64_t p) {
    asm("mov.b64 {%0, %1}, %2;" : "=f"(lo), "=f"(hi) : "l"(p));
}
__device__ __forceinline__ uint64_t add2(uint64_t a, uint64_t b) {
    uint64_t r; asm("add.rn.f32x2 %0, %1, %2;" : "=l"(r) : "l"(a), "l"(b)); return r;
}
__device__ __forceinline__ uint64_t mul2(uint64_t a, uint64_t b) {
    uint64_t r; asm("mul.rn.f32x2 %0, %1, %2;" : "=l"(r) : "l"(a), "l"(b)); return r;
}
__device__ __forceinline__ uint64_t fma2(uint64_t a, uint64_t b, uint64_t c) {
    uint64_t r; asm("fma.rn.f32x2 %0, %1, %2, %3;" : "=l"(r) : "l"(a), "l"(b), "l"(c)); return r;
}

// ---------------------------------------------------------------------------
// FPS kernel: one 8-CTA cluster per batch. R4-proven skeleton (cluster.sync
// exchange; mbarrier variants measured slower in R5/R7). Per iteration:
//   all warps: packed-f32x2 distance update + per-thread argmax (value +
//     local j only) -> warp REDUX -> winner lane recovers coords, writes
//     s_warp[wid] -> __syncthreads
//   warp0: block REDUX over 16 warp winners; lanes 0..7 fan the CTA
//     candidate out to every rank's double-buffered DSMEM slot
//   cluster.sync()
//   all warps: REDUX combine over the 8 slots -> global winner + coords.
//
// Tie-break everywhere: max value, then MIN global index (= jnp.argmax
// first-occurrence; indices globally unique so matches are one-hot). Value
// bits as u32 max is exact for nonnegative floats.
//
// Distance formula replicates XLA/NVPTX fp contraction exactly (bit-exact in
// R2/R4/R5/R6/R7), evaluated per lane of the packed ops:
//   d = fma(dz, dz, fma(dx, dx, dy*dy)),  dx = px + (-cx)  (== px - cx, IEEE)
// ---------------------------------------------------------------------------
__global__ void __cluster_dims__(CSIZE, 1, 1) __launch_bounds__(TPB, 1)
fps_kernel(const float* __restrict__ xyz)
{
    cg::cluster_group cluster = cg::this_cluster();
    const int rank  = cluster.block_rank();
    const int batch = blockIdx.x / CSIZE;
    const int tid   = threadIdx.x;
    const int lane  = tid & 31;
    const int wid   = tid >> 5;

    const float* __restrict__ xb = xyz + (size_t)batch * NPTS * 3;

    __shared__ alignas(16) float s_warp[NWARP][8];      // per-warp winners
    __shared__ alignas(16) float s_slot[2][CSIZE][8];   // cluster candidates

    const int base = rank * PPC + tid;

    // Register-resident coords (scalar, for winner recovery) + packed copies
    // (for the distance pipeline) + running min distances.
    float px[PPT], py[PPT], pz[PPT], md[PPT];
#pragma unroll
    for (int j = 0; j < PPT; j++) {
        const int p = base + j * TPB;
        px[j] = xb[3 * p + 0];
        py[j] = xb[3 * p + 1];
        pz[j] = xb[3 * p + 2];
        md[j] = 1e10f;            // BIG from the reference
    }
    uint64_t px2[NPAIR], py2[NPAIR], pz2[NPAIR];
#pragma unroll
    for (int i = 0; i < NPAIR; i++) {
        px2[i] = pk2(px[2 * i], px[2 * i + 1]);
        py2[i] = pk2(py[2 * i], py[2 * i + 1]);
        pz2[i] = pk2(pz[2 * i], pz[2 * i + 1]);
    }

    // First sampled point is index 0 (deterministic variant).
    float cx = xb[0], cy = xb[1], cz = xb[2];
    if (rank == 0 && tid == 0) g_idx[batch * NSAMP] = 0;

    for (int k = 1; k < NSAMP; k++) {
        // --- per-thread: packed distance update, argmax (value + local j) ---
        const uint64_t ncx2 = pk2(-cx, -cx);
        const uint64_t ncy2 = pk2(-cy, -cy);
        const uint64_t ncz2 = pk2(-cz, -cz);
        float bv;
        int   bj;
#pragma unroll
        for (int i = 0; i < NPAIR; i++) {
            const uint64_t dx2 = add2(px2[i], ncx2);   // px - cx (exact)
            const uint64_t dy2 = add2(py2[i], ncy2);
            const uint64_t dz2 = add2(pz2[i], ncz2);
            const uint64_t dp  = fma2(dz2, dz2,
                                  fma2(dx2, dx2, mul2(dy2, dy2)));
            float d0, d1;
            upk2(d0, d1, dp);
            {
                const float m = fminf(md[2 * i], d0);
                md[2 * i] = m;
                if (i == 0) { bv = m; bj = 0; }
                else if (m > bv) { bv = m; bj = 2 * i; }   // strict >: low j wins
            }
            {
                const float m = fminf(md[2 * i + 1], d1);
                md[2 * i + 1] = m;
                if (m > bv) { bv = m; bj = 2 * i + 1; }
            }
        }
        const uint32_t bi = (uint32_t)(base + bj * TPB);

        // --- warp argmax via REDUX ---
        const uint32_t uv = __float_as_uint(bv);            // bv >= 0
        const uint32_t kv = __reduce_max_sync(0xffffffffu, uv);
        const uint32_t cand = (uv == kv) ? bi : 0xffffffffu;
        const uint32_t ki = __reduce_min_sync(0xffffffffu, cand);
        if (bi == ki) {            // unique winner lane: recover coords here
            float bx = px[0], by = py[0], bz = pz[0];
#pragma unroll
            for (int j = 1; j < PPT; j++) {
                if (bj == j) { bx = px[j]; by = py[j]; bz = pz[j]; }
            }
            *(float4*)&s_warp[wid][0] =
                make_float4(__uint_as_float(kv), __uint_as_float(ki), bx, by);
            s_warp[wid][4] = bz;
        }
        __syncthreads();

        const int b = k & 1;

        // --- warp0: block argmax over 16 warp winners, fan out to all ranks ---
        if (wid == 0) {
            float sv = 0.f, sx = 0.f, sy = 0.f, sz = 0.f;
            uint32_t si = 0xffffffffu;
            if (lane < NWARP) {
                const float4 t = *(const float4*)&s_warp[lane][0];
                sv = t.x; si = __float_as_uint(t.y); sx = t.z; sy = t.w;
                sz = s_warp[lane][4];
            }
            const uint32_t uv2 = __float_as_uint(sv);
            const uint32_t kv2 = __reduce_max_sync(0xffffffffu, uv2);
            const uint32_t c2  = (uv2 == kv2) ? si : 0xffffffffu;
            const uint32_t ki2 = __reduce_min_sync(0xffffffffu, c2);
            const uint32_t m2  = __ballot_sync(0xffffffffu, c2 == ki2); // one-hot
            const int src = __ffs(m2) - 1;
            const float wx = __shfl_sync(0xffffffffu, sx, src);
            const float wy = __shfl_sync(0xffffffffu, sy, src);
            const float wz = __shfl_sync(0xffffffffu, sz, src);
            if (lane < CSIZE) {
                // lane r writes this CTA's candidate into rank r's slot row.
                // Ordering/visibility provided by cluster.sync() below.
                float* dst = (float*)cluster.map_shared_rank(
                    (void*)&s_slot[b][rank][0], lane);
                *(float4*)dst =
                    make_float4(__uint_as_float(kv2), __uint_as_float(ki2), wx, wy);
                dst[4] = wz;
            }
        }

        // release DSMEM stores + cluster barrier + acquire remote stores
        cluster.sync();

        // --- per-warp REDUX combine over the CSIZE slots ---
        float sv = 0.f, sx = 0.f, sy = 0.f, sz = 0.f;
        uint32_t si = 0xffffffffu;
        if (lane < CSIZE) {
            const float4 t = *(const float4*)&s_slot[b][lane][0];
            sv = t.x; si = __float_as_uint(t.y); sx = t.z; sy = t.w;
            sz = s_slot[b][lane][4];
        }
        const uint32_t uv3 = __float_as_uint(sv);
        const uint32_t kv3 = __reduce_max_sync(0xffffffffu, uv3);
        const uint32_t c3  = (uv3 == kv3) ? si : 0xffffffffu;
        const uint32_t ki3 = __reduce_min_sync(0xffffffffu, c3);
        const uint32_t m3  = __ballot_sync(0xffffffffu, c3 == ki3);    // one-hot
        const int src3 = __ffs(m3) - 1;
        cx = __shfl_sync(0xffffffffu, sx, src3);
        cy = __shfl_sync(0xffffffffu, sy, src3);
        cz = __shfl_sync(0xffffffffu, sz, src3);

        if (rank == 0 && tid == 0) g_idx[batch * NSAMP + k] = (int)ki3;
    }
}

// ---------------------------------------------------------------------------
// Gather kernel: one block per sampled row. 256 feature floats (64 x float4)
// plus the 3 xyz floats. Output: [xyz (B,S,3)] then [feature (B,S,256)].
// ---------------------------------------------------------------------------
__global__ void __launch_bounds__(64)
gather_kernel(const float* __restrict__ xyz, const float* __restrict__ feat,
              float* __restrict__ out)
{
    const int row = blockIdx.x;          // 0 .. BATCH*NSAMP-1
    const int b = row / NSAMP;
    const int p = g_idx[row];

    float* out_xyz  = out;
    float* out_feat = out + (size_t)BATCH * NSAMP * 3;

    const float4* src = (const float4*)(feat + ((size_t)b * NPTS + p) * FEATC);
    float4*       dst = (float4*)(out_feat + (size_t)row * FEATC);
    dst[threadIdx.x] = src[threadIdx.x];

    if (threadIdx.x < 3) {
        out_xyz[(size_t)row * 3 + threadIdx.x] =
            xyz[((size_t)b * NPTS + p) * 3 + threadIdx.x];
    }
}

extern "C" void kernel_launch(void* const* d_in, const int* in_sizes, int n_in,
                              void* d_out, int out_size)
{
    const float* xyz  = (const float*)d_in[0];
    const float* feat = (const float*)d_in[1];
    float*       out  = (float*)d_out;

    fps_kernel<<<BATCH * CSIZE, TPB>>>(xyz);
    gather_kernel<<<BATCH * NSAMP, 64>>>(xyz, feat, out);
}